// round 13
// baseline (speedup 1.0000x reference)
#include <cuda_runtime.h>
#include <cuda_fp16.h>
#include <cstdint>

#define N_NODES 100000
#define D 128
#define CAP 128                // bucket capacity per node (Poisson(16) tail ~ e^-40)
#define NB 64                  // nodes per GEMM tile
#define WSH 136                // smem stride in halves; bank=(4*row+tg)%32 conflict-free
#define NUM_TILES ((N_NODES + NB - 1) / NB)

// ---- scratch (module-load allocations, allowed) ----
__device__ __half2 g_hh[(size_t)N_NODES * 64];  // normalized h rows, fp16
__device__ __half2 g_fh[(size_t)N_NODES * 64];  // fp16-packed features
__device__ int g_cur[N_NODES];                  // per-node cursor == degree
__device__ int g_bucket[(size_t)N_NODES * CAP]; // neighbor src lists
__device__ int g_idx64;                         // edge index width flag
__device__ int g_mask_stride;                   // bytes per mask element

// ---------------------------------------------------------------------------
// Init: zero cursors; block 0 detects edge-index width + mask stride.
// ---------------------------------------------------------------------------
__global__ void init_kernel(const unsigned long long* src,
                            const unsigned char* mask) {
    int gid = blockIdx.x * blockDim.x + threadIdx.x;
    if (gid < N_NODES) g_cur[gid] = 0;

    if (blockIdx.x != 0) return;
    __shared__ int bad, nzres;
    if (threadIdx.x == 0) { bad = 0; nzres = 0; }
    __syncthreads();
    for (int i = threadIdx.x; i < 1024; i += blockDim.x)
        if (src[i] >= (unsigned long long)N_NODES) bad = 1;
    for (int i = threadIdx.x; i < 8192; i += blockDim.x)
        if (mask[i]) atomicOr(&nzres, 1 << (i & 7));
    __syncthreads();
    if (threadIdx.x == 0) {
        g_idx64 = bad ? 0 : 1;
        int m = nzres, s;
        if (m == 0)        s = 1;
        else if (m & 0xAA) s = 1;
        else if (m & 0x44) s = 2;
        else if (m & 0x10) s = 4;
        else               s = 8;
        g_mask_stride = s;
    }
}

// ---------------------------------------------------------------------------
// Fused: fp32->fp16 feature convert (DRAM-read bound) + edge placement
// (L2-atomic bound). Independent resources -> overlap in one kernel.
// ---------------------------------------------------------------------------
__global__ void place_conv_kernel(const void* __restrict__ src_idx,
                                  const void* __restrict__ dst_idx,
                                  const float* __restrict__ feat,
                                  int n_edges) {
    int gid = blockIdx.x * blockDim.x + threadIdx.x;
    int gs = gridDim.x * blockDim.x;

    // Convert features to fp16 (only reader of feat in the whole pipeline).
    const float4* f4 = (const float4*)feat;
    int total = N_NODES * 32;
    for (int i = gid; i < total; i += gs) {
        float4 v = f4[i];
        __half2 lo = __floats2half2_rn(v.x, v.y);
        __half2 hi = __floats2half2_rn(v.z, v.w);
        uint2 pk;
        pk.x = *(uint32_t*)&lo;
        pk.y = *(uint32_t*)&hi;
        *(uint2*)&g_fh[2 * i] = pk;
    }

    // Place edges into fixed-capacity buckets. Cursor == degree.
    int idx64 = g_idx64;
    for (int e = gid; e < n_edges; e += gs) {
        int s, d;
        if (idx64) {
            s = (int)((const long long*)src_idx)[e];
            d = (int)((const long long*)dst_idx)[e];
        } else {
            s = ((const int*)src_idx)[e];
            d = ((const int*)dst_idx)[e];
        }
        int pos = atomicAdd(&g_cur[d], 1);
        if (pos < CAP) g_bucket[(size_t)d * CAP + pos] = s;
    }
}

// ---------------------------------------------------------------------------
// Gather (fp16 rows incl. self, one LDG.64 per edge-lane) + L2-normalize.
// One warp per node, lane holds 4 columns. Writes fp16 h rows.
// ---------------------------------------------------------------------------
__device__ __forceinline__ void add_row(float4& acc, uint2 u) {
    float2 f0 = __half22float2(*(__half2*)&u.x);
    float2 f1 = __half22float2(*(__half2*)&u.y);
    acc.x += f0.x; acc.y += f0.y; acc.z += f1.x; acc.w += f1.y;
}

__global__ __launch_bounds__(256)
void gather_norm_kernel(const unsigned char* __restrict__ mask) {
    int n = blockIdx.x * 8 + (threadIdx.x >> 5);
    int lane = threadIdx.x & 31;
    if (n >= N_NODES) return;
    int mstride = g_mask_stride;
    const __half2* fh = g_fh;

    float4 acc = make_float4(0.f, 0.f, 0.f, 0.f);
    add_row(acc, ((const uint2*)(fh + (size_t)n * 64))[lane]);

    if (mask[(size_t)n * mstride]) {
        int deg = g_cur[n];
        if (deg > CAP) deg = CAP;
        const int* bucket = g_bucket + (size_t)n * CAP;
        int e = 0;
        for (; e + 4 <= deg; e += 4) {
            int s0 = bucket[e + 0], s1 = bucket[e + 1];
            int s2 = bucket[e + 2], s3 = bucket[e + 3];
            uint2 u0 = ((const uint2*)(fh + (size_t)s0 * 64))[lane];
            uint2 u1 = ((const uint2*)(fh + (size_t)s1 * 64))[lane];
            uint2 u2 = ((const uint2*)(fh + (size_t)s2 * 64))[lane];
            uint2 u3 = ((const uint2*)(fh + (size_t)s3 * 64))[lane];
            add_row(acc, u0);
            add_row(acc, u1);
            add_row(acc, u2);
            add_row(acc, u3);
        }
        for (; e < deg; e++) {
            int s0 = bucket[e];
            add_row(acc, ((const uint2*)(fh + (size_t)s0 * 64))[lane]);
        }
    }

    float ss = acc.x * acc.x + acc.y * acc.y + acc.z * acc.z + acc.w * acc.w;
#pragma unroll
    for (int o = 16; o > 0; o >>= 1) ss += __shfl_xor_sync(0xFFFFFFFFu, ss, o);
    float inv = 1.f / fmaxf(sqrtf(ss), 1e-12f);

    __half2 h0 = __floats2half2_rn(acc.x * inv, acc.y * inv);
    __half2 h1 = __floats2half2_rn(acc.z * inv, acc.w * inv);
    uint2 pk;
    pk.x = *(uint32_t*)&h0;
    pk.y = *(uint32_t*)&h1;
    ((uint2*)g_hh)[(size_t)n * 32 + lane] = pk;
}

// ---------------------------------------------------------------------------
// GEMM via mma.sync.m16n8k16.f16.f32 (fp32 accumulate).
// A fragments loaded DIRECTLY from global g_hh (8.5KB/tile, L1-resident,
// each element read by 2 warps) -> no Hs smem, no per-tile __syncthreads.
// Warps stream tiles independently; scheduler overlaps LDG latency with MMA.
// 256 threads = 8 warps; block tile 64 nodes x 128 outputs; smem = W only.
// ---------------------------------------------------------------------------
__device__ __forceinline__ void mma_f16(float* d, const uint32_t* a,
                                        uint32_t b0, uint32_t b1) {
    asm volatile(
        "mma.sync.aligned.m16n8k16.row.col.f32.f16.f16.f32 "
        "{%0,%1,%2,%3}, {%4,%5,%6,%7}, {%8,%9}, {%0,%1,%2,%3};"
        : "+f"(d[0]), "+f"(d[1]), "+f"(d[2]), "+f"(d[3])
        : "r"(a[0]), "r"(a[1]), "r"(a[2]), "r"(a[3]), "r"(b0), "r"(b1));
}

__global__ __launch_bounds__(256, 2)
void gemm_kernel(const float* __restrict__ W,
                 const float* __restrict__ b,
                 float* __restrict__ out) {
    extern __shared__ __align__(16) __half smh[];
    __half* Wsm = smh;                       // 128 * WSH halves
    float* bsm  = (float*)(smh + 128 * WSH); // 128 floats

    int t = threadIdx.x;
    int lane = t & 31, wid = t >> 5;
    int grp = lane >> 2, tg = lane & 3;
    int wm = wid & 3, wn = wid >> 2;

    // Stage W (fp16-rounded) once per block.
    for (int idx = t; idx < 128 * 128; idx += 256) {
        int r = idx >> 7, c = idx & 127;
        Wsm[r * WSH + c] = __float2half_rn(W[idx]);
    }
    if (t < 128) bsm[t] = b[t];
    __syncthreads();

    for (int g = blockIdx.x; g < NUM_TILES; g += gridDim.x) {
        int base = g * NB;
        int r0 = base + wm * 16 + grp;
        int r1 = r0 + 8;
        // Clamp fragment row reads for the final partial tile (stores stay
        // guarded by the real r0/r1, so clamped rows never escape).
        int r0c = r0 < N_NODES ? r0 : N_NODES - 1;
        int r1c = r1 < N_NODES ? r1 : N_NODES - 1;
        const uint32_t* arow0 = (const uint32_t*)(g_hh + (size_t)r0c * 64);
        const uint32_t* arow1 = (const uint32_t*)(g_hh + (size_t)r1c * 64);

        float d[8][4];
#pragma unroll
        for (int nt = 0; nt < 8; nt++)
#pragma unroll
            for (int q = 0; q < 4; q++) d[nt][q] = 0.f;

#pragma unroll
        for (int ks = 0; ks < 8; ks++) {
            int k0 = ks * 16;
            uint32_t a[4];
            a[0] = arow0[ks * 8 + tg];       // halves k0 + 2*tg
            a[1] = arow1[ks * 8 + tg];
            a[2] = arow0[ks * 8 + tg + 4];   // halves k0 + 8 + 2*tg
            a[3] = arow1[ks * 8 + tg + 4];
#pragma unroll
            for (int nt = 0; nt < 8; nt++) {
                const __half* br = Wsm + (wn * 64 + nt * 8 + grp) * WSH + k0 + 2 * tg;
                uint32_t b0 = *(const uint32_t*)(br);
                uint32_t b1 = *(const uint32_t*)(br + 8);
                mma_f16(d[nt], a, b0, b1);
            }
        }

        // Epilogue: add bias, float2 stores.
#pragma unroll
        for (int nt = 0; nt < 8; nt++) {
            int col = wn * 64 + nt * 8 + 2 * tg;
            float2 bias = *(float2*)&bsm[col];
            if (r0 < N_NODES) {
                float2 v = make_float2(d[nt][0] + bias.x, d[nt][1] + bias.y);
                *(float2*)&out[(size_t)r0 * D + col] = v;
            }
            if (r1 < N_NODES) {
                float2 v = make_float2(d[nt][2] + bias.x, d[nt][3] + bias.y);
                *(float2*)&out[(size_t)r1 * D + col] = v;
            }
        }
    }
}

// ---------------------------------------------------------------------------
extern "C" void kernel_launch(void* const* d_in, const int* in_sizes, int n_in,
                              void* d_out, int out_size) {
    const float*         feat = (const float*)d_in[0];
    const void*          esrc = d_in[1];
    const void*          edst = d_in[2];
    const unsigned char* mask = (const unsigned char*)d_in[3];
    const float*         W    = (const float*)d_in[4];
    const float*         b    = (const float*)d_in[5];
    float*               out  = (float*)d_out;
    int n_edges = in_sizes[1];

    init_kernel<<<(N_NODES + 255) / 256, 256>>>(
        (const unsigned long long*)esrc, mask);

    place_conv_kernel<<<2048, 256>>>(esrc, edst, feat, n_edges);

    gather_norm_kernel<<<(N_NODES + 7) / 8, 256>>>(mask);

    size_t smem = (size_t)(128 * WSH) * sizeof(__half) + 128 * sizeof(float);
    cudaFuncSetAttribute(gemm_kernel,
                         cudaFuncAttributeMaxDynamicSharedMemorySize,
                         (int)smem);
    gemm_kernel<<<296, 256, smem>>>(W, b, out);
}

// round 14
// speedup vs baseline: 1.0884x; 1.0884x over previous
#include <cuda_runtime.h>
#include <cuda_fp16.h>
#include <cstdint>

#define N_NODES 100000
#define D 128
#define CAP 128                // bucket capacity per node (Poisson(16) tail ~ e^-40)
#define NB 64                  // nodes per GEMM tile
#define WSH 136                // smem stride in halves; bank=(4*row+tg)%32 conflict-free
#define NUM_TILES ((N_NODES + NB - 1) / NB)

// ---- scratch (module-load allocations, allowed) ----
__device__ __half2 g_hh[(size_t)N_NODES * 64];  // normalized h rows, fp16
__device__ __half2 g_fh[(size_t)N_NODES * 64];  // fp16-packed features
__device__ int g_cur[N_NODES];                  // per-node cursor == degree
__device__ int g_bucket[(size_t)N_NODES * CAP]; // neighbor src lists
__device__ int g_idx64;                         // edge index width flag
__device__ int g_mask_stride;                   // bytes per mask element

// ---------------------------------------------------------------------------
// Init: zero cursors; block 0 detects edge-index width + mask stride.
// ---------------------------------------------------------------------------
__global__ void init_kernel(const unsigned long long* src,
                            const unsigned char* mask) {
    int gid = blockIdx.x * blockDim.x + threadIdx.x;
    if (gid < N_NODES) g_cur[gid] = 0;

    if (blockIdx.x != 0) return;
    __shared__ int bad, nzres;
    if (threadIdx.x == 0) { bad = 0; nzres = 0; }
    __syncthreads();
    for (int i = threadIdx.x; i < 1024; i += blockDim.x)
        if (src[i] >= (unsigned long long)N_NODES) bad = 1;
    for (int i = threadIdx.x; i < 8192; i += blockDim.x)
        if (mask[i]) atomicOr(&nzres, 1 << (i & 7));
    __syncthreads();
    if (threadIdx.x == 0) {
        g_idx64 = bad ? 0 : 1;
        int m = nzres, s;
        if (m == 0)        s = 1;
        else if (m & 0xAA) s = 1;
        else if (m & 0x44) s = 2;
        else if (m & 0x10) s = 4;
        else               s = 8;
        g_mask_stride = s;
    }
}

// ---------------------------------------------------------------------------
// Fused: fp32->fp16 feature convert (DRAM-read bound) + edge placement
// (L2-atomic bound). Independent resources -> overlap in one kernel.
// ---------------------------------------------------------------------------
__global__ void place_conv_kernel(const void* __restrict__ src_idx,
                                  const void* __restrict__ dst_idx,
                                  const float* __restrict__ feat,
                                  int n_edges) {
    int gid = blockIdx.x * blockDim.x + threadIdx.x;
    int gs = gridDim.x * blockDim.x;

    // Convert features to fp16 (only reader of feat in the whole pipeline).
    const float4* f4 = (const float4*)feat;
    int total = N_NODES * 32;
    for (int i = gid; i < total; i += gs) {
        float4 v = f4[i];
        __half2 lo = __floats2half2_rn(v.x, v.y);
        __half2 hi = __floats2half2_rn(v.z, v.w);
        uint2 pk;
        pk.x = *(uint32_t*)&lo;
        pk.y = *(uint32_t*)&hi;
        *(uint2*)&g_fh[2 * i] = pk;
    }

    // Place edges into fixed-capacity buckets. Cursor == degree.
    int idx64 = g_idx64;
    for (int e = gid; e < n_edges; e += gs) {
        int s, d;
        if (idx64) {
            s = (int)((const long long*)src_idx)[e];
            d = (int)((const long long*)dst_idx)[e];
        } else {
            s = ((const int*)src_idx)[e];
            d = ((const int*)dst_idx)[e];
        }
        int pos = atomicAdd(&g_cur[d], 1);
        if (pos < CAP) g_bucket[(size_t)d * CAP + pos] = s;
    }
}

// ---------------------------------------------------------------------------
// Gather (fp16 rows incl. self, one LDG.64 per edge-lane) + L2-normalize.
// One warp per node, lane holds 4 columns. Writes fp16 h rows.
// ---------------------------------------------------------------------------
__device__ __forceinline__ void add_row(float4& acc, uint2 u) {
    float2 f0 = __half22float2(*(__half2*)&u.x);
    float2 f1 = __half22float2(*(__half2*)&u.y);
    acc.x += f0.x; acc.y += f0.y; acc.z += f1.x; acc.w += f1.y;
}

__global__ __launch_bounds__(256)
void gather_norm_kernel(const unsigned char* __restrict__ mask) {
    int n = blockIdx.x * 8 + (threadIdx.x >> 5);
    int lane = threadIdx.x & 31;
    if (n >= N_NODES) return;
    int mstride = g_mask_stride;
    const __half2* fh = g_fh;

    float4 acc = make_float4(0.f, 0.f, 0.f, 0.f);
    add_row(acc, ((const uint2*)(fh + (size_t)n * 64))[lane]);

    if (mask[(size_t)n * mstride]) {
        int deg = g_cur[n];
        if (deg > CAP) deg = CAP;
        const int* bucket = g_bucket + (size_t)n * CAP;
        int e = 0;
        for (; e + 4 <= deg; e += 4) {
            int s0 = bucket[e + 0], s1 = bucket[e + 1];
            int s2 = bucket[e + 2], s3 = bucket[e + 3];
            uint2 u0 = ((const uint2*)(fh + (size_t)s0 * 64))[lane];
            uint2 u1 = ((const uint2*)(fh + (size_t)s1 * 64))[lane];
            uint2 u2 = ((const uint2*)(fh + (size_t)s2 * 64))[lane];
            uint2 u3 = ((const uint2*)(fh + (size_t)s3 * 64))[lane];
            add_row(acc, u0);
            add_row(acc, u1);
            add_row(acc, u2);
            add_row(acc, u3);
        }
        for (; e < deg; e++) {
            int s0 = bucket[e];
            add_row(acc, ((const uint2*)(fh + (size_t)s0 * 64))[lane]);
        }
    }

    float ss = acc.x * acc.x + acc.y * acc.y + acc.z * acc.z + acc.w * acc.w;
#pragma unroll
    for (int o = 16; o > 0; o >>= 1) ss += __shfl_xor_sync(0xFFFFFFFFu, ss, o);
    float inv = 1.f / fmaxf(sqrtf(ss), 1e-12f);

    __half2 h0 = __floats2half2_rn(acc.x * inv, acc.y * inv);
    __half2 h1 = __floats2half2_rn(acc.z * inv, acc.w * inv);
    uint2 pk;
    pk.x = *(uint32_t*)&h0;
    pk.y = *(uint32_t*)&h1;
    ((uint2*)g_hh)[(size_t)n * 32 + lane] = pk;
}

// ---------------------------------------------------------------------------
// GEMM via mma.sync.m16n8k16.f16.f32, cp.async double-buffered Hs staging.
// 256 threads = 8 warps; block tile 64 nodes x 128 outputs; 2 CTAs/SM.
// Warp (wm=wid&3, wn=wid>>2): tile 16 nodes x 64 outputs.
// Tile g+2's staging issued right after tile g's compute -> staging latency
// hidden behind a full tile of MMA+epilogue. Partial-tile rows clamped
// (garbage pollutes only never-stored output rows).
// ---------------------------------------------------------------------------
__device__ __forceinline__ void mma_f16(float* d, const uint32_t* a,
                                        uint32_t b0, uint32_t b1) {
    asm volatile(
        "mma.sync.aligned.m16n8k16.row.col.f32.f16.f16.f32 "
        "{%0,%1,%2,%3}, {%4,%5,%6,%7}, {%8,%9}, {%0,%1,%2,%3};"
        : "+f"(d[0]), "+f"(d[1]), "+f"(d[2]), "+f"(d[3])
        : "r"(a[0]), "r"(a[1]), "r"(a[2]), "r"(a[3]), "r"(b0), "r"(b1));
}

__device__ __forceinline__ uint32_t smem_u32(const void* p) {
    uint32_t a;
    asm("{ .reg .u64 t; cvta.to.shared.u64 t, %1; cvt.u32.u64 %0, t; }"
        : "=r"(a) : "l"(p));
    return a;
}

// Stage one 64-row fp16 tile into Hs buffer via cp.async.cg (16B each).
__device__ __forceinline__ void stage_tile(uint32_t hs_addr, int tile, int t) {
    int base = tile * NB;
#pragma unroll
    for (int k = 0; k < 4; k++) {
        int idx = t + k * 256;              // 0..1023
        int nl = idx >> 4, c16 = idx & 15;
        int n = base + nl;
        if (n >= N_NODES) n = N_NODES - 1;  // clamp; rows never stored
        const char* src = (const char*)g_hh + (size_t)n * 256 + c16 * 16;
        uint32_t dst = hs_addr + nl * (WSH * 2) + c16 * 16;
        asm volatile("cp.async.cg.shared.global [%0], [%1], 16;"
                     :: "r"(dst), "l"(src));
    }
}

__global__ __launch_bounds__(256, 2)
void gemm_kernel(const float* __restrict__ W,
                 const float* __restrict__ b,
                 float* __restrict__ out) {
    extern __shared__ __align__(16) __half smh[];
    __half* Wsm = smh;                            // 128 * WSH halves
    __half* Hs0 = smh + 128 * WSH;                // 64 * WSH halves
    __half* Hs1 = Hs0 + NB * WSH;                 // 64 * WSH halves
    float* bsm  = (float*)(Hs1 + NB * WSH);       // 128 floats

    int t = threadIdx.x;
    int lane = t & 31, wid = t >> 5;
    int grp = lane >> 2, tg = lane & 3;
    int wm = wid & 3, wn = wid >> 2;

    uint32_t hs_addr[2] = { smem_u32(Hs0), smem_u32(Hs1) };
    __half* hs_ptr[2] = { Hs0, Hs1 };

    // Stage W (fp16-rounded) once per block.
    for (int idx = t; idx < 128 * 128; idx += 256) {
        int r = idx >> 7, c = idx & 127;
        Wsm[r * WSH + c] = __float2half_rn(W[idx]);
    }
    if (t < 128) bsm[t] = b[t];

    // Prime the pipeline: stage tiles g0 and g0+step.
    int gstep = gridDim.x;
    int g0 = blockIdx.x;
    if (g0 < NUM_TILES) stage_tile(hs_addr[0], g0, t);
    asm volatile("cp.async.commit_group;" ::: "memory");
    if (g0 + gstep < NUM_TILES) stage_tile(hs_addr[1], g0 + gstep, t);
    asm volatile("cp.async.commit_group;" ::: "memory");

    __syncthreads();   // W/bias visible (cp.async still in flight)

    int buf = 0;
    for (int g = g0; g < NUM_TILES; g += gstep) {
        asm volatile("cp.async.wait_group 1;" ::: "memory");
        __syncthreads();                   // current buffer ready for all

        const __half* Hs = hs_ptr[buf];
        int base = g * NB;

        float d[8][4];
#pragma unroll
        for (int nt = 0; nt < 8; nt++)
#pragma unroll
            for (int q = 0; q < 4; q++) d[nt][q] = 0.f;

#pragma unroll
        for (int ks = 0; ks < 8; ks++) {
            int k0 = ks * 16;
            uint32_t a[4];
            const __half* ar = Hs + (wm * 16 + grp) * WSH + k0 + 2 * tg;
            a[0] = *(const uint32_t*)(ar);
            a[1] = *(const uint32_t*)(ar + 8 * WSH);
            a[2] = *(const uint32_t*)(ar + 8);
            a[3] = *(const uint32_t*)(ar + 8 * WSH + 8);
#pragma unroll
            for (int nt = 0; nt < 8; nt++) {
                const __half* br = Wsm + (wn * 64 + nt * 8 + grp) * WSH + k0 + 2 * tg;
                uint32_t b0 = *(const uint32_t*)(br);
                uint32_t b1 = *(const uint32_t*)(br + 8);
                mma_f16(d[nt], a, b0, b1);
            }
        }

        // Epilogue: add bias, float2 stores.
        {
            int r0 = base + wm * 16 + grp;
            int r1 = r0 + 8;
#pragma unroll
            for (int nt = 0; nt < 8; nt++) {
                int col = wn * 64 + nt * 8 + 2 * tg;
                float2 bias = *(float2*)&bsm[col];
                if (r0 < N_NODES) {
                    float2 v = make_float2(d[nt][0] + bias.x,
                                           d[nt][1] + bias.y);
                    *(float2*)&out[(size_t)r0 * D + col] = v;
                }
                if (r1 < N_NODES) {
                    float2 v = make_float2(d[nt][2] + bias.x,
                                           d[nt][3] + bias.y);
                    *(float2*)&out[(size_t)r1 * D + col] = v;
                }
            }
        }
        __syncthreads();                   // all reads of buf done

        int nxt2 = g + 2 * gstep;
        if (nxt2 < NUM_TILES) stage_tile(hs_addr[buf], nxt2, t);
        asm volatile("cp.async.commit_group;" ::: "memory");
        buf ^= 1;
    }
}

// ---------------------------------------------------------------------------
extern "C" void kernel_launch(void* const* d_in, const int* in_sizes, int n_in,
                              void* d_out, int out_size) {
    const float*         feat = (const float*)d_in[0];
    const void*          esrc = d_in[1];
    const void*          edst = d_in[2];
    const unsigned char* mask = (const unsigned char*)d_in[3];
    const float*         W    = (const float*)d_in[4];
    const float*         b    = (const float*)d_in[5];
    float*               out  = (float*)d_out;
    int n_edges = in_sizes[1];

    init_kernel<<<(N_NODES + 255) / 256, 256>>>(
        (const unsigned long long*)esrc, mask);

    place_conv_kernel<<<2048, 256>>>(esrc, edst, feat, n_edges);

    gather_norm_kernel<<<(N_NODES + 7) / 8, 256>>>(mask);

    size_t smem = (size_t)(128 * WSH + 2 * NB * WSH) * sizeof(__half)
                + 128 * sizeof(float);
    cudaFuncSetAttribute(gemm_kernel,
                         cudaFuncAttributeMaxDynamicSharedMemorySize,
                         (int)smem);
    gemm_kernel<<<296, 256, smem>>>(W, b, out);
}